// round 10
// baseline (speedup 1.0000x reference)
#include <cuda_runtime.h>

#define NN   100000
#define NE   1600000
#define FIN  128
#define DIM  32
#define NC   40
#define CAP  128          // per-node bucket capacity (Poisson(16) -> P(>128) ~ 1e-80)

#define NB_EDGE ((NE + 255) / 256)     // 6250
#define NB_NODE ((NN + 255) / 256)     // 391

// ---------------- scratch (device globals — no runtime alloc) ----------------
__device__ __align__(16) float g_y   [(size_t)NN * DIM];
__device__ __align__(16) float g_aggY[(size_t)NN * DIM];
__device__ __align__(16) float g_z   [(size_t)NN * DIM];
__device__ __align__(16) float g_aggZ[(size_t)NN * DIM];
__device__ __align__(16) int   g_slot[(size_t)NN * CAP];   // bucketed CSC
__device__ __align__(16) int   g_deg [NN];
__device__ int g_is64;
__device__ __align__(16) float g_W2a [DIM * DIM];   // diag(s1) @ w2a
__device__ __align__(16) float g_c2a [DIM];         // (bn1_b - bn1_m*s1) @ w2a
__device__ __align__(16) float g_W2b [DIM * DIM];   // w2b @ diag(s2)
__device__ __align__(16) float g_bb2 [DIM];         // (b2b - bn2_m)*s2 + bn2_b

// ---------------- f32x2 packed-FMA helpers ----------------
typedef unsigned long long u64;
__device__ __forceinline__ void fma2(u64& d, u64 a, u64 b) {
    asm("fma.rn.f32x2 %0, %1, %2, %0;" : "+l"(d) : "l"(a), "l"(b));
}
__device__ __forceinline__ u64 bcast2(float a) {
    u64 v; asm("mov.b64 %0, {%1, %1};" : "=l"(v) : "f"(a)); return v;
}
__device__ __forceinline__ u64 pk2(float a, float b) {
    u64 v; asm("mov.b64 %0, {%1, %2};" : "=l"(v) : "f"(a), "f"(b)); return v;
}
__device__ __forceinline__ float2 up2(u64 v) {
    float2 f; asm("mov.b64 {%0, %1}, %2;" : "=f"(f.x), "=f"(f.y) : "l"(v)); return f;
}

// ---------------- init+setup: detect dtype, zero deg, fold BN (one launch) ----------------
__global__ void __launch_bounds__(1024) k_initsetup(
    const int* __restrict__ ei32,
    const float* __restrict__ w2a,
    const float* __restrict__ bn1_g, const float* __restrict__ bn1_b,
    const float* __restrict__ bn1_m, const float* __restrict__ bn1_v,
    const float* __restrict__ w2b,  const float* __restrict__ b2b,
    const float* __restrict__ bn2_g, const float* __restrict__ bn2_b,
    const float* __restrict__ bn2_m, const float* __restrict__ bn2_v) {
    int tid = threadIdx.x;
    if (blockIdx.x == 0) {
        if (tid == 0) {
            int all_zero = 1;
            for (int q = 1; q < 128; q += 2)
                if (ei32[q] != 0) { all_zero = 0; break; }
            g_is64 = all_zero;
        }
        int k = tid >> 5, j = tid & 31;
        float s1k = bn1_g[k] * rsqrtf(bn1_v[k] + 1e-5f);
        g_W2a[tid] = s1k * w2a[tid];
        float s2j = bn2_g[j] * rsqrtf(bn2_v[j] + 1e-5f);
        g_W2b[tid] = w2b[tid] * s2j;
        if (tid < DIM) {
            float c = 0.f;
            for (int kk = 0; kk < DIM; kk++) {
                float s = bn1_g[kk] * rsqrtf(bn1_v[kk] + 1e-5f);
                c += (bn1_b[kk] - bn1_m[kk] * s) * w2a[kk * DIM + tid];
            }
            g_c2a[tid] = c;
            float s2 = bn2_g[tid] * rsqrtf(bn2_v[tid] + 1e-5f);
            g_bb2[tid] = (b2b[tid] - bn2_m[tid]) * s2 + bn2_b[tid];
        }
    } else {
        int i = (blockIdx.x - 1) * 1024 + tid;
        if (i < NN) g_deg[i] = 0;
    }
}

// ---------------- fused: CSC fill (blocks [0,NB_EDGE)) + gemm1 (rest) ----------------
__global__ void __launch_bounds__(256) k_fillgemm(const int* __restrict__ ei32,
                                                  const float* __restrict__ x,
                                                  const float* __restrict__ w1a) {
    if (blockIdx.x < NB_EDGE) {
        int e = blockIdx.x * 256 + threadIdx.x;
        if (e >= NE) return;
        int s, d;
        if (g_is64) {
            s = ((const int2*)ei32)[e].x;                    // LDG.64, low word
            d = ((const int2*)ei32)[(size_t)NE + e].x;
        } else {
            s = ei32[e];
            d = ei32[NE + e];
        }
        int pos = atomicAdd(&g_deg[d], 1);
        if (pos < CAP) g_slot[(size_t)d * CAP + pos] = s;
        return;
    }

    // ---- gemm1 path ----
    __shared__ float4 ws[FIN * (DIM / 4)];            // 16 KB
    for (int i = threadIdx.x; i < FIN * DIM / 4; i += 256)
        ws[i] = ((const float4*)w1a)[i];
    __syncthreads();

    int n = (blockIdx.x - NB_EDGE) * 256 + threadIdx.x;
    if (n >= NN) return;

    u64 acc[DIM / 2];
#pragma unroll
    for (int j = 0; j < DIM / 2; j++) acc[j] = 0ull;

    const float4* xr = (const float4*)(x + (size_t)n * FIN);
    for (int kk = 0; kk < FIN / 4; kk++) {
        float4 xv = xr[kk];
#pragma unroll
        for (int u = 0; u < 4; u++) {
            float xs = (u == 0) ? xv.x : (u == 1) ? xv.y : (u == 2) ? xv.z : xv.w;
            u64 xs2 = bcast2(xs);
            const u64* wr = (const u64*)&ws[(kk * 4 + u) * 8];
#pragma unroll
            for (int j2 = 0; j2 < 16; j2++)
                fma2(acc[j2], xs2, wr[j2]);
        }
    }
    u64* yr = (u64*)(g_y + (size_t)n * DIM);
#pragma unroll
    for (int j2 = 0; j2 < 16; j2++) yr[j2] = acc[j2];
}

// ---------------- gather-sum: warp per node, 4 neighbor-groups x 8 float4 lanes ----------------
template <int PASS>
__global__ void __launch_bounds__(256) k_gather() {
    int warp = (blockIdx.x * 256 + threadIdx.x) >> 5;
    int lane = threadIdx.x & 31;
    if (warp >= NN) return;

    const float* feat = (PASS == 0) ? g_y    : g_z;
    float*       agg  = (PASS == 0) ? g_aggY : g_aggZ;

    int grp = lane >> 3;          // neighbor group 0..3
    int col = lane & 7;           // float4 column 0..7

    const int* bucket = &g_slot[(size_t)warp * CAP];
    int cnt = g_deg[warp];
    if (cnt > CAP) cnt = CAP;

    float4 acc = make_float4(0.f, 0.f, 0.f, 0.f);
#pragma unroll 2
    for (int p = 0; p < cnt; p += 4) {
        int nb = p + grp;
        if (nb < cnt) {
            int s = __ldg(&bucket[nb]);                        // 8-lane broadcast
            float4 v = __ldg((const float4*)(feat + (size_t)s * DIM) + col);
            acc.x += v.x; acc.y += v.y; acc.z += v.z; acc.w += v.w;
        }
    }
#pragma unroll
    for (int off = 16; off >= 8; off >>= 1) {
        acc.x += __shfl_xor_sync(0xffffffffu, acc.x, off);
        acc.y += __shfl_xor_sync(0xffffffffu, acc.y, off);
        acc.z += __shfl_xor_sync(0xffffffffu, acc.z, off);
        acc.w += __shfl_xor_sync(0xffffffffu, acc.w, off);
    }
    if (grp == 0)
        ((float4*)(agg + (size_t)warp * DIM))[col] = acc;
}

// ---------------- K3: chunked GEMVs (8 u64 accumulators live) for occupancy ----------------
__global__ void __launch_bounds__(256, 4) k_mlp1(const float* __restrict__ b1a,
                                                 const float* __restrict__ w1b,
                                                 const float* __restrict__ b1b) {
    __shared__ float4 w1b_s[DIM * 8];
    __shared__ float4 w2a_s[DIM * 8];
    __shared__ float b1a_s[DIM], b1b_s[DIM], c2a_s[DIM];
    int t = threadIdx.x;
    for (int i = t; i < DIM * 8; i += 256) {
        w1b_s[i] = ((const float4*)w1b)[i];
        w2a_s[i] = ((const float4*)g_W2a)[i];
    }
    if (t < DIM) { b1a_s[t] = b1a[t]; b1b_s[t] = b1b[t]; c2a_s[t] = g_c2a[t]; }
    __syncthreads();

    int n = blockIdx.x * 256 + t;
    if (n >= NN) return;

    float tin[DIM];
    const float4* ay = (const float4*)(g_aggY + (size_t)n * DIM);
    const float4* yy = (const float4*)(g_y    + (size_t)n * DIM);
#pragma unroll
    for (int i = 0; i < 8; i++) {
        float4 a = ay[i], b = yy[i];
        tin[i*4+0] = fmaxf(a.x + b.x + b1a_s[i*4+0], 0.f);
        tin[i*4+1] = fmaxf(a.y + b.y + b1a_s[i*4+1], 0.f);
        tin[i*4+2] = fmaxf(a.z + b.z + b1a_s[i*4+2], 0.f);
        tin[i*4+3] = fmaxf(a.w + b.w + b1a_s[i*4+3], 0.f);
    }

    // h = relu(tin @ w1b + b1b), computed in two 16-col chunks
    float hr[DIM];
    const u64* w1b_u = (const u64*)w1b_s;          // row stride 16 u64
#pragma unroll
    for (int hh = 0; hh < 2; hh++) {
        u64 acc[8];
#pragma unroll
        for (int j = 0; j < 8; j++) acc[j] = pk2(b1b_s[hh*16 + 2*j], b1b_s[hh*16 + 2*j + 1]);
#pragma unroll
        for (int k = 0; k < DIM; k++) {
            u64 tk2 = bcast2(tin[k]);
#pragma unroll
            for (int j = 0; j < 8; j++) fma2(acc[j], tk2, w1b_u[k*16 + hh*8 + j]);
        }
#pragma unroll
        for (int j = 0; j < 8; j++) {
            float2 f = up2(acc[j]);
            hr[hh*16 + 2*j]     = fmaxf(f.x, 0.f);
            hr[hh*16 + 2*j + 1] = fmaxf(f.y, 0.f);
        }
    }

    // z = hr @ W2a' + c2a, two chunks, stored directly
    u64* zr = (u64*)(g_z + (size_t)n * DIM);
    const u64* w2a_u = (const u64*)w2a_s;
#pragma unroll
    for (int hh = 0; hh < 2; hh++) {
        u64 acc[8];
#pragma unroll
        for (int j = 0; j < 8; j++) acc[j] = pk2(c2a_s[hh*16 + 2*j], c2a_s[hh*16 + 2*j + 1]);
#pragma unroll
        for (int k = 0; k < DIM; k++) {
            u64 rk2 = bcast2(hr[k]);
#pragma unroll
            for (int j = 0; j < 8; j++) fma2(acc[j], rk2, w2a_u[k*16 + hh*8 + j]);
        }
#pragma unroll
        for (int j = 0; j < 8; j++) zr[hh*8 + j] = acc[j];
    }
}

// ---------------- K5: epilogue + log_softmax, chunked GEMVs ----------------
__global__ void __launch_bounds__(256, 3) k_final(const float* __restrict__ b2a,
                                                  const float* __restrict__ fc1_w,
                                                  const float* __restrict__ fc1_b,
                                                  const float* __restrict__ fc2_w,
                                                  const float* __restrict__ fc2_b,
                                                  float* __restrict__ out) {
    __shared__ float4 w2b_s[DIM * 8];
    __shared__ float4 fc1_s[DIM * 8];
    __shared__ float4 fc2_s[DIM * NC / 4];
    __shared__ float b2a_s[DIM], bb2_s[DIM], fc1b_s[DIM], fc2b_s[NC];
    int t = threadIdx.x;
    for (int i = t; i < DIM * 8; i += 256) {
        w2b_s[i] = ((const float4*)g_W2b)[i];
        fc1_s[i] = ((const float4*)fc1_w)[i];
    }
    for (int i = t; i < DIM * NC / 4; i += 256)
        fc2_s[i] = ((const float4*)fc2_w)[i];
    if (t < DIM) { b2a_s[t] = b2a[t]; bb2_s[t] = g_bb2[t]; fc1b_s[t] = fc1_b[t]; }
    if (t < NC)  fc2b_s[t] = fc2_b[t];
    __syncthreads();

    int n = blockIdx.x * 256 + t;
    if (n >= NN) return;

    // q = relu(aggZ + z + b2a)
    float q[DIM];
    const float4* az = (const float4*)(g_aggZ + (size_t)n * DIM);
    const float4* zz = (const float4*)(g_z    + (size_t)n * DIM);
#pragma unroll
    for (int i = 0; i < 8; i++) {
        float4 a = az[i], b = zz[i];
        q[i*4+0] = fmaxf(a.x + b.x + b2a_s[i*4+0], 0.f);
        q[i*4+1] = fmaxf(a.y + b.y + b2a_s[i*4+1], 0.f);
        q[i*4+2] = fmaxf(a.z + b.z + b2a_s[i*4+2], 0.f);
        q[i*4+3] = fmaxf(a.w + b.w + b2a_s[i*4+3], 0.f);
    }

    // u = q @ W2b' + b2b', chunked
    float uf[DIM];
    const u64* w2b_u = (const u64*)w2b_s;
#pragma unroll
    for (int hh = 0; hh < 2; hh++) {
        u64 acc[8];
#pragma unroll
        for (int j = 0; j < 8; j++) acc[j] = pk2(bb2_s[hh*16 + 2*j], bb2_s[hh*16 + 2*j + 1]);
#pragma unroll
        for (int k = 0; k < DIM; k++) {
            u64 qk2 = bcast2(q[k]);
#pragma unroll
            for (int j = 0; j < 8; j++) fma2(acc[j], qk2, w2b_u[k*16 + hh*8 + j]);
        }
#pragma unroll
        for (int j = 0; j < 8; j++) {
            float2 f = up2(acc[j]);
            uf[hh*16 + 2*j] = f.x; uf[hh*16 + 2*j + 1] = f.y;
        }
    }

    // r = relu(u @ fc1_w + fc1_b), chunked
    float rf[DIM];
    const u64* fc1_u = (const u64*)fc1_s;
#pragma unroll
    for (int hh = 0; hh < 2; hh++) {
        u64 acc[8];
#pragma unroll
        for (int j = 0; j < 8; j++) acc[j] = pk2(fc1b_s[hh*16 + 2*j], fc1b_s[hh*16 + 2*j + 1]);
#pragma unroll
        for (int k = 0; k < DIM; k++) {
            u64 uk2 = bcast2(uf[k]);
#pragma unroll
            for (int j = 0; j < 8; j++) fma2(acc[j], uk2, fc1_u[k*16 + hh*8 + j]);
        }
#pragma unroll
        for (int j = 0; j < 8; j++) {
            float2 f = up2(acc[j]);
            rf[hh*16 + 2*j]     = fmaxf(f.x, 0.f);
            rf[hh*16 + 2*j + 1] = fmaxf(f.y, 0.f);
        }
    }

    // logits = r @ fc2_w + fc2_b (32 x 40), chunked into 2 x 20 cols
    float lf[NC];
    const u64* fc2_u = (const u64*)fc2_s;          // row stride 20 u64
#pragma unroll
    for (int hh = 0; hh < 2; hh++) {
        u64 acc[10];
#pragma unroll
        for (int c = 0; c < 10; c++) acc[c] = pk2(fc2b_s[hh*20 + 2*c], fc2b_s[hh*20 + 2*c + 1]);
#pragma unroll
        for (int k = 0; k < DIM; k++) {
            u64 rk2 = bcast2(rf[k]);
#pragma unroll
            for (int c = 0; c < 10; c++) fma2(acc[c], rk2, fc2_u[k*20 + hh*10 + c]);
        }
#pragma unroll
        for (int c = 0; c < 10; c++) {
            float2 f = up2(acc[c]);
            lf[hh*20 + 2*c] = f.x; lf[hh*20 + 2*c + 1] = f.y;
        }
    }

    // log_softmax
    float m = lf[0];
#pragma unroll
    for (int c = 1; c < NC; c++) m = fmaxf(m, lf[c]);
    float ssum = 0.f;
#pragma unroll
    for (int c = 0; c < NC; c++) ssum += expf(lf[c] - m);
    float lse = m + logf(ssum);

    float4* orow = (float4*)(out + (size_t)n * NC);
#pragma unroll
    for (int c4 = 0; c4 < NC / 4; c4++)
        orow[c4] = make_float4(lf[c4*4+0]-lse, lf[c4*4+1]-lse, lf[c4*4+2]-lse, lf[c4*4+3]-lse);
}

// ---------------- launch ----------------
extern "C" void kernel_launch(void* const* d_in, const int* in_sizes, int n_in,
                              void* d_out, int out_size) {
    const float* x     = (const float*)d_in[0];
    const int*   ei32  = (const int*)d_in[1];       // int32 OR int64 (detected on device)
    const float* w1a   = (const float*)d_in[2];
    const float* b1a   = (const float*)d_in[3];
    const float* w1b   = (const float*)d_in[4];
    const float* b1b   = (const float*)d_in[5];
    const float* w2a   = (const float*)d_in[6];
    const float* b2a   = (const float*)d_in[7];
    const float* w2b   = (const float*)d_in[8];
    const float* b2b   = (const float*)d_in[9];
    const float* bn1_g = (const float*)d_in[10];
    const float* bn1_b = (const float*)d_in[11];
    const float* bn1_m = (const float*)d_in[12];
    const float* bn1_v = (const float*)d_in[13];
    const float* bn2_g = (const float*)d_in[14];
    const float* bn2_b = (const float*)d_in[15];
    const float* bn2_m = (const float*)d_in[16];
    const float* bn2_v = (const float*)d_in[17];
    const float* fc1_w = (const float*)d_in[18];
    const float* fc1_b = (const float*)d_in[19];
    const float* fc2_w = (const float*)d_in[20];
    const float* fc2_b = (const float*)d_in[21];
    float* out = (float*)d_out;

    const int NB_WARP = (NN * 32 + 255) / 256;      // 12500, warp per node
    const int NB_INIT = 1 + (NN + 1023) / 1024;     // 99

    // 6 launches; profiled (4th) launch is k_mlp1 (verifying the occupancy fix)
    k_initsetup<<<NB_INIT, 1024>>>(ei32, w2a, bn1_g, bn1_b, bn1_m, bn1_v,
                                   w2b, b2b, bn2_g, bn2_b, bn2_m, bn2_v);
    k_fillgemm<<<NB_EDGE + NB_NODE, 256>>>(ei32, x, w1a);
    k_gather<0><<<NB_WARP, 256>>>();
    k_mlp1<<<NB_NODE, 256>>>(b1a, w1b, b1b);
    k_gather<1><<<NB_WARP, 256>>>();
    k_final<<<NB_NODE, 256>>>(b2a, fc1_w, fc1_b, fc2_w, fc2_b, out);
}

// round 12
// speedup vs baseline: 1.0032x; 1.0032x over previous
#include <cuda_runtime.h>

#define NN   100000
#define NE   1600000
#define FIN  128
#define DIM  32
#define NC   40
#define CAP  128          // per-node bucket capacity (Poisson(16) -> P(>128) ~ 1e-80)

#define NB_EDGE ((NE + 255) / 256)     // 6250
#define NB_NODE ((NN + 255) / 256)     // 391

// ---------------- scratch (device globals — no runtime alloc) ----------------
__device__ __align__(16) float g_y   [(size_t)NN * DIM];
__device__ __align__(16) float g_aggY[(size_t)NN * DIM];
__device__ __align__(16) float g_z   [(size_t)NN * DIM];
__device__ __align__(16) float g_aggZ[(size_t)NN * DIM];
__device__ __align__(16) int   g_slot[(size_t)NN * CAP];   // bucketed CSC
__device__ __align__(16) int   g_deg [NN];
__device__ int g_is64;
__device__ __align__(16) float g_W2a [DIM * DIM];   // diag(s1) @ w2a
__device__ __align__(16) float g_c2a [DIM];         // (bn1_b - bn1_m*s1) @ w2a
__device__ __align__(16) float g_W2b [DIM * DIM];   // w2b @ diag(s2)
__device__ __align__(16) float g_bb2 [DIM];         // (b2b - bn2_m)*s2 + bn2_b

// ---------------- f32x2 packed-FMA helpers ----------------
typedef unsigned long long u64;
__device__ __forceinline__ void fma2(u64& d, u64 a, u64 b) {
    asm("fma.rn.f32x2 %0, %1, %2, %0;" : "+l"(d) : "l"(a), "l"(b));
}
__device__ __forceinline__ u64 bcast2(float a) {
    u64 v; asm("mov.b64 %0, {%1, %1};" : "=l"(v) : "f"(a)); return v;
}
__device__ __forceinline__ u64 pk2(float a, float b) {
    u64 v; asm("mov.b64 %0, {%1, %2};" : "=l"(v) : "f"(a), "f"(b)); return v;
}
__device__ __forceinline__ float2 up2(u64 v) {
    float2 f; asm("mov.b64 {%0, %1}, %2;" : "=f"(f.x), "=f"(f.y) : "l"(v)); return f;
}

// ---------------- init+setup: detect dtype, zero deg, fold BN (one launch) ----------------
__global__ void __launch_bounds__(1024) k_initsetup(
    const int* __restrict__ ei32,
    const float* __restrict__ w2a,
    const float* __restrict__ bn1_g, const float* __restrict__ bn1_b,
    const float* __restrict__ bn1_m, const float* __restrict__ bn1_v,
    const float* __restrict__ w2b,  const float* __restrict__ b2b,
    const float* __restrict__ bn2_g, const float* __restrict__ bn2_b,
    const float* __restrict__ bn2_m, const float* __restrict__ bn2_v) {
    int tid = threadIdx.x;
    if (blockIdx.x == 0) {
        if (tid == 0) {
            int all_zero = 1;
            for (int q = 1; q < 128; q += 2)
                if (ei32[q] != 0) { all_zero = 0; break; }
            g_is64 = all_zero;
        }
        int k = tid >> 5, j = tid & 31;
        float s1k = bn1_g[k] * rsqrtf(bn1_v[k] + 1e-5f);
        g_W2a[tid] = s1k * w2a[tid];
        float s2j = bn2_g[j] * rsqrtf(bn2_v[j] + 1e-5f);
        g_W2b[tid] = w2b[tid] * s2j;
        if (tid < DIM) {
            float c = 0.f;
            for (int kk = 0; kk < DIM; kk++) {
                float s = bn1_g[kk] * rsqrtf(bn1_v[kk] + 1e-5f);
                c += (bn1_b[kk] - bn1_m[kk] * s) * w2a[kk * DIM + tid];
            }
            g_c2a[tid] = c;
            float s2 = bn2_g[tid] * rsqrtf(bn2_v[tid] + 1e-5f);
            g_bb2[tid] = (b2b[tid] - bn2_m[tid]) * s2 + bn2_b[tid];
        }
    } else {
        int i = (blockIdx.x - 1) * 1024 + tid;
        if (i < NN) g_deg[i] = 0;
    }
}

// ---------------- fused: CSC fill (blocks [0,NB_EDGE)) + gemm1 (rest) ----------------
__global__ void __launch_bounds__(256) k_fillgemm(const int* __restrict__ ei32,
                                                  const float* __restrict__ x,
                                                  const float* __restrict__ w1a) {
    if (blockIdx.x < NB_EDGE) {
        int e = blockIdx.x * 256 + threadIdx.x;
        if (e >= NE) return;
        int s, d;
        if (g_is64) {
            s = ((const int2*)ei32)[e].x;                    // LDG.64, low word
            d = ((const int2*)ei32)[(size_t)NE + e].x;
        } else {
            s = ei32[e];
            d = ei32[NE + e];
        }
        int pos = atomicAdd(&g_deg[d], 1);
        if (pos < CAP) g_slot[(size_t)d * CAP + pos] = s;
        return;
    }

    // ---- gemm1 path ----
    __shared__ float4 ws[FIN * (DIM / 4)];            // 16 KB
    for (int i = threadIdx.x; i < FIN * DIM / 4; i += 256)
        ws[i] = ((const float4*)w1a)[i];
    __syncthreads();

    int n = (blockIdx.x - NB_EDGE) * 256 + threadIdx.x;
    if (n >= NN) return;

    u64 acc[DIM / 2];
#pragma unroll
    for (int j = 0; j < DIM / 2; j++) acc[j] = 0ull;

    const float4* xr = (const float4*)(x + (size_t)n * FIN);
    for (int kk = 0; kk < FIN / 4; kk++) {
        float4 xv = xr[kk];
#pragma unroll
        for (int u = 0; u < 4; u++) {
            float xs = (u == 0) ? xv.x : (u == 1) ? xv.y : (u == 2) ? xv.z : xv.w;
            u64 xs2 = bcast2(xs);
            const ulonglong2* wr = (const ulonglong2*)&ws[(kk * 4 + u) * 8];
#pragma unroll
            for (int j4 = 0; j4 < 8; j4++) {
                ulonglong2 w = wr[j4];                 // LDS.128 -> 2 fma2
                fma2(acc[2*j4],     xs2, w.x);
                fma2(acc[2*j4 + 1], xs2, w.y);
            }
        }
    }
    u64* yr = (u64*)(g_y + (size_t)n * DIM);
#pragma unroll
    for (int j2 = 0; j2 < 16; j2++) yr[j2] = acc[j2];
}

// ---------------- gather-sum: warp per node, 4 neighbor-groups x 8 float4 lanes ----------------
template <int PASS>
__global__ void __launch_bounds__(256) k_gather() {
    int warp = (blockIdx.x * 256 + threadIdx.x) >> 5;
    int lane = threadIdx.x & 31;
    if (warp >= NN) return;

    const float* feat = (PASS == 0) ? g_y    : g_z;
    float*       agg  = (PASS == 0) ? g_aggY : g_aggZ;

    int grp = lane >> 3;          // neighbor group 0..3
    int col = lane & 7;           // float4 column 0..7

    const int* bucket = &g_slot[(size_t)warp * CAP];
    int cnt = g_deg[warp];
    if (cnt > CAP) cnt = CAP;

    float4 acc = make_float4(0.f, 0.f, 0.f, 0.f);
#pragma unroll 2
    for (int p = 0; p < cnt; p += 4) {
        int nb = p + grp;
        if (nb < cnt) {
            int s = __ldg(&bucket[nb]);                        // 8-lane broadcast
            float4 v = __ldg((const float4*)(feat + (size_t)s * DIM) + col);
            acc.x += v.x; acc.y += v.y; acc.z += v.z; acc.w += v.w;
        }
    }
#pragma unroll
    for (int off = 16; off >= 8; off >>= 1) {
        acc.x += __shfl_xor_sync(0xffffffffu, acc.x, off);
        acc.y += __shfl_xor_sync(0xffffffffu, acc.y, off);
        acc.z += __shfl_xor_sync(0xffffffffu, acc.z, off);
        acc.w += __shfl_xor_sync(0xffffffffu, acc.w, off);
    }
    if (grp == 0)
        ((float4*)(agg + (size_t)warp * DIM))[col] = acc;
}

// ---------------- K3: z = relu(relu(aggY+y+b1a)@w1b + b1b) @ W2a' + c', LDS.128 ----------------
__global__ void __launch_bounds__(256) k_mlp1(const float* __restrict__ b1a,
                                              const float* __restrict__ w1b,
                                              const float* __restrict__ b1b) {
    __shared__ float4 w1b_s[DIM * 8];
    __shared__ float4 w2a_s[DIM * 8];
    __shared__ float b1a_s[DIM], b1b_s[DIM], c2a_s[DIM];
    int t = threadIdx.x;
    for (int i = t; i < DIM * 8; i += 256) {
        w1b_s[i] = ((const float4*)w1b)[i];
        w2a_s[i] = ((const float4*)g_W2a)[i];
    }
    if (t < DIM) { b1a_s[t] = b1a[t]; b1b_s[t] = b1b[t]; c2a_s[t] = g_c2a[t]; }
    __syncthreads();

    int n = blockIdx.x * 256 + t;
    if (n >= NN) return;

    float tin[DIM];
    const float4* ay = (const float4*)(g_aggY + (size_t)n * DIM);
    const float4* yy = (const float4*)(g_y    + (size_t)n * DIM);
#pragma unroll
    for (int i = 0; i < 8; i++) {
        float4 a = ay[i], b = yy[i];
        tin[i*4+0] = fmaxf(a.x + b.x + b1a_s[i*4+0], 0.f);
        tin[i*4+1] = fmaxf(a.y + b.y + b1a_s[i*4+1], 0.f);
        tin[i*4+2] = fmaxf(a.z + b.z + b1a_s[i*4+2], 0.f);
        tin[i*4+3] = fmaxf(a.w + b.w + b1a_s[i*4+3], 0.f);
    }

    u64 h[DIM / 2];
#pragma unroll
    for (int j = 0; j < DIM / 2; j++) h[j] = pk2(b1b_s[2*j], b1b_s[2*j+1]);
#pragma unroll
    for (int k = 0; k < DIM; k++) {
        u64 tk2 = bcast2(tin[k]);
        const ulonglong2* wr = (const ulonglong2*)&w1b_s[k * 8];
#pragma unroll
        for (int j4 = 0; j4 < 8; j4++) {
            ulonglong2 w = wr[j4];
            fma2(h[2*j4],     tk2, w.x);
            fma2(h[2*j4 + 1], tk2, w.y);
        }
    }

    float hr[DIM];
#pragma unroll
    for (int j2 = 0; j2 < 16; j2++) {
        float2 f = up2(h[j2]);
        hr[2*j2]   = fmaxf(f.x, 0.f);
        hr[2*j2+1] = fmaxf(f.y, 0.f);
    }

    u64 z[DIM / 2];
#pragma unroll
    for (int j = 0; j < DIM / 2; j++) z[j] = pk2(c2a_s[2*j], c2a_s[2*j+1]);
#pragma unroll
    for (int k = 0; k < DIM; k++) {
        u64 rk2 = bcast2(hr[k]);
        const ulonglong2* wr = (const ulonglong2*)&w2a_s[k * 8];
#pragma unroll
        for (int j4 = 0; j4 < 8; j4++) {
            ulonglong2 w = wr[j4];
            fma2(z[2*j4],     rk2, w.x);
            fma2(z[2*j4 + 1], rk2, w.y);
        }
    }

    u64* zr = (u64*)(g_z + (size_t)n * DIM);
#pragma unroll
    for (int j2 = 0; j2 < 16; j2++) zr[j2] = z[j2];
}

// ---------------- K5: epilogue + log_softmax, LDS.128 ----------------
__global__ void __launch_bounds__(256) k_final(const float* __restrict__ b2a,
                                               const float* __restrict__ fc1_w,
                                               const float* __restrict__ fc1_b,
                                               const float* __restrict__ fc2_w,
                                               const float* __restrict__ fc2_b,
                                               float* __restrict__ out) {
    __shared__ float4 w2b_s[DIM * 8];
    __shared__ float4 fc1_s[DIM * 8];
    __shared__ float4 fc2_s[DIM * NC / 4];
    __shared__ float b2a_s[DIM], bb2_s[DIM], fc1b_s[DIM], fc2b_s[NC];
    int t = threadIdx.x;
    for (int i = t; i < DIM * 8; i += 256) {
        w2b_s[i] = ((const float4*)g_W2b)[i];
        fc1_s[i] = ((const float4*)fc1_w)[i];
    }
    for (int i = t; i < DIM * NC / 4; i += 256)
        fc2_s[i] = ((const float4*)fc2_w)[i];
    if (t < DIM) { b2a_s[t] = b2a[t]; bb2_s[t] = g_bb2[t]; fc1b_s[t] = fc1_b[t]; }
    if (t < NC)  fc2b_s[t] = fc2_b[t];
    __syncthreads();

    int n = blockIdx.x * 256 + t;
    if (n >= NN) return;

    // q = relu(aggZ + z + b2a)
    float q[DIM];
    const float4* az = (const float4*)(g_aggZ + (size_t)n * DIM);
    const float4* zz = (const float4*)(g_z    + (size_t)n * DIM);
#pragma unroll
    for (int i = 0; i < 8; i++) {
        float4 a = az[i], b = zz[i];
        q[i*4+0] = fmaxf(a.x + b.x + b2a_s[i*4+0], 0.f);
        q[i*4+1] = fmaxf(a.y + b.y + b2a_s[i*4+1], 0.f);
        q[i*4+2] = fmaxf(a.z + b.z + b2a_s[i*4+2], 0.f);
        q[i*4+3] = fmaxf(a.w + b.w + b2a_s[i*4+3], 0.f);
    }

    // u = q @ W2b' + b2b'
    u64 u[DIM / 2];
#pragma unroll
    for (int j = 0; j < DIM / 2; j++) u[j] = pk2(bb2_s[2*j], bb2_s[2*j+1]);
#pragma unroll
    for (int k = 0; k < DIM; k++) {
        u64 qk2 = bcast2(q[k]);
        const ulonglong2* wr = (const ulonglong2*)&w2b_s[k * 8];
#pragma unroll
        for (int j4 = 0; j4 < 8; j4++) {
            ulonglong2 w = wr[j4];
            fma2(u[2*j4],     qk2, w.x);
            fma2(u[2*j4 + 1], qk2, w.y);
        }
    }
    float uf[DIM];
#pragma unroll
    for (int j2 = 0; j2 < 16; j2++) {
        float2 f = up2(u[j2]);
        uf[2*j2] = f.x; uf[2*j2+1] = f.y;
    }

    // r = relu(u @ fc1_w + fc1_b)
    u64 r[DIM / 2];
#pragma unroll
    for (int j = 0; j < DIM / 2; j++) r[j] = pk2(fc1b_s[2*j], fc1b_s[2*j+1]);
#pragma unroll
    for (int k = 0; k < DIM; k++) {
        u64 uk2 = bcast2(uf[k]);
        const ulonglong2* wr = (const ulonglong2*)&fc1_s[k * 8];
#pragma unroll
        for (int j4 = 0; j4 < 8; j4++) {
            ulonglong2 w = wr[j4];
            fma2(r[2*j4],     uk2, w.x);
            fma2(r[2*j4 + 1], uk2, w.y);
        }
    }
    float rf[DIM];
#pragma unroll
    for (int j2 = 0; j2 < 16; j2++) {
        float2 f = up2(r[j2]);
        rf[2*j2]   = fmaxf(f.x, 0.f);
        rf[2*j2+1] = fmaxf(f.y, 0.f);
    }

    // logits = r @ fc2_w + fc2_b   (32 x 40): row = 10 ulonglong2 -> 20 u64 accumulators
    u64 l[NC / 2];
#pragma unroll
    for (int c = 0; c < NC / 2; c++) l[c] = pk2(fc2b_s[2*c], fc2b_s[2*c+1]);
#pragma unroll
    for (int k = 0; k < DIM; k++) {
        u64 rk2 = bcast2(rf[k]);
        const ulonglong2* wr = (const ulonglong2*)&fc2_s[k * (NC / 4)];
#pragma unroll
        for (int c2 = 0; c2 < NC / 4; c2++) {        // 10 ulonglong2 per row (FIXED)
            ulonglong2 w = wr[c2];
            fma2(l[2*c2],     rk2, w.x);
            fma2(l[2*c2 + 1], rk2, w.y);
        }
    }
    float lf[NC];
#pragma unroll
    for (int c2 = 0; c2 < NC / 2; c2++) {
        float2 f = up2(l[c2]);
        lf[2*c2] = f.x; lf[2*c2+1] = f.y;
    }

    // log_softmax
    float m = lf[0];
#pragma unroll
    for (int c = 1; c < NC; c++) m = fmaxf(m, lf[c]);
    float ssum = 0.f;
#pragma unroll
    for (int c = 0; c < NC; c++) ssum += expf(lf[c] - m);
    float lse = m + logf(ssum);

    float4* orow = (float4*)(out + (size_t)n * NC);
#pragma unroll
    for (int c4 = 0; c4 < NC / 4; c4++)
        orow[c4] = make_float4(lf[c4*4+0]-lse, lf[c4*4+1]-lse, lf[c4*4+2]-lse, lf[c4*4+3]-lse);
}

// ---------------- launch ----------------
extern "C" void kernel_launch(void* const* d_in, const int* in_sizes, int n_in,
                              void* d_out, int out_size) {
    const float* x     = (const float*)d_in[0];
    const int*   ei32  = (const int*)d_in[1];       // int32 OR int64 (detected on device)
    const float* w1a   = (const float*)d_in[2];
    const float* b1a   = (const float*)d_in[3];
    const float* w1b   = (const float*)d_in[4];
    const float* b1b   = (const float*)d_in[5];
    const float* w2a   = (const float*)d_in[6];
    const float* b2a   = (const float*)d_in[7];
    const float* w2b   = (const float*)d_in[8];
    const float* b2b   = (const float*)d_in[9];
    const float* bn1_g = (const float*)d_in[10];
    const float* bn1_b = (const float*)d_in[11];
    const float* bn1_m = (const float*)d_in[12];
    const float* bn1_v = (const float*)d_in[13];
    const float* bn2_g = (const float*)d_in[14];
    const float* bn2_b = (const float*)d_in[15];
    const float* bn2_m = (const float*)d_in[16];
    const float* bn2_v = (const float*)d_in[17];
    const float* fc1_w = (const float*)d_in[18];
    const float* fc1_b = (const float*)d_in[19];
    const float* fc2_w = (const float*)d_in[20];
    const float* fc2_b = (const float*)d_in[21];
    float* out = (float*)d_out;

    const int NB_WARP = (NN * 32 + 255) / 256;      // 12500, warp per node
    const int NB_INIT = 1 + (NN + 1023) / 1024;     // 99

    // 6 launches; profiled (4th) launch is k_mlp1 (verifying the LDS.128 fix)
    k_initsetup<<<NB_INIT, 1024>>>(ei32, w2a, bn1_g, bn1_b, bn1_m, bn1_v,
                                   w2b, b2b, bn2_g, bn2_b, bn2_m, bn2_v);
    k_fillgemm<<<NB_EDGE + NB_NODE, 256>>>(ei32, x, w1a);
    k_gather<0><<<NB_WARP, 256>>>();
    k_mlp1<<<NB_NODE, 256>>>(b1a, w1b, b1b);
    k_gather<1><<<NB_WARP, 256>>>();
    k_final<<<NB_NODE, 256>>>(b2a, fc1_w, fc1_b, fc2_w, fc2_b, out);
}

// round 13
// speedup vs baseline: 1.0239x; 1.0206x over previous
#include <cuda_runtime.h>

#define NN   100000
#define NE   1600000
#define FIN  128
#define DIM  32
#define NC   40
#define CAP  128          // per-node bucket capacity (Poisson(16) -> P(>128) ~ 1e-80)
#define SAS  33           // smem activation stride (conflict-free: (33t+k)%32=(t+k)%32)

#define NB_EDGE ((NE + 255) / 256)     // 6250
#define NB_NODE ((NN + 255) / 256)     // 391

// ---------------- scratch (device globals — no runtime alloc) ----------------
__device__ __align__(16) float g_y   [(size_t)NN * DIM];
__device__ __align__(16) float g_aggY[(size_t)NN * DIM];
__device__ __align__(16) float g_z   [(size_t)NN * DIM];
__device__ __align__(16) float g_aggZ[(size_t)NN * DIM];
__device__ __align__(16) int   g_slot[(size_t)NN * CAP];   // bucketed CSC
__device__ __align__(16) int   g_deg [NN];
__device__ int g_is64;
__device__ __align__(16) float g_W2a [DIM * DIM];   // diag(s1) @ w2a
__device__ __align__(16) float g_c2a [DIM];         // (bn1_b - bn1_m*s1) @ w2a
__device__ __align__(16) float g_W2b [DIM * DIM];   // w2b @ diag(s2)
__device__ __align__(16) float g_bb2 [DIM];         // (b2b - bn2_m)*s2 + bn2_b

// ---------------- f32x2 packed-FMA helpers ----------------
typedef unsigned long long u64;
__device__ __forceinline__ void fma2(u64& d, u64 a, u64 b) {
    asm("fma.rn.f32x2 %0, %1, %2, %0;" : "+l"(d) : "l"(a), "l"(b));
}
__device__ __forceinline__ u64 bcast2(float a) {
    u64 v; asm("mov.b64 %0, {%1, %1};" : "=l"(v) : "f"(a)); return v;
}
__device__ __forceinline__ u64 pk2(float a, float b) {
    u64 v; asm("mov.b64 %0, {%1, %2};" : "=l"(v) : "f"(a), "f"(b)); return v;
}
__device__ __forceinline__ float2 up2(u64 v) {
    float2 f; asm("mov.b64 {%0, %1}, %2;" : "=f"(f.x), "=f"(f.y) : "l"(v)); return f;
}

// ---------------- init+setup: detect dtype, zero deg, fold BN (one launch) ----------------
__global__ void __launch_bounds__(1024) k_initsetup(
    const int* __restrict__ ei32,
    const float* __restrict__ w2a,
    const float* __restrict__ bn1_g, const float* __restrict__ bn1_b,
    const float* __restrict__ bn1_m, const float* __restrict__ bn1_v,
    const float* __restrict__ w2b,  const float* __restrict__ b2b,
    const float* __restrict__ bn2_g, const float* __restrict__ bn2_b,
    const float* __restrict__ bn2_m, const float* __restrict__ bn2_v) {
    int tid = threadIdx.x;
    if (blockIdx.x == 0) {
        if (tid == 0) {
            int all_zero = 1;
            for (int q = 1; q < 128; q += 2)
                if (ei32[q] != 0) { all_zero = 0; break; }
            g_is64 = all_zero;
        }
        int k = tid >> 5, j = tid & 31;
        float s1k = bn1_g[k] * rsqrtf(bn1_v[k] + 1e-5f);
        g_W2a[tid] = s1k * w2a[tid];
        float s2j = bn2_g[j] * rsqrtf(bn2_v[j] + 1e-5f);
        g_W2b[tid] = w2b[tid] * s2j;
        if (tid < DIM) {
            float c = 0.f;
            for (int kk = 0; kk < DIM; kk++) {
                float s = bn1_g[kk] * rsqrtf(bn1_v[kk] + 1e-5f);
                c += (bn1_b[kk] - bn1_m[kk] * s) * w2a[kk * DIM + tid];
            }
            g_c2a[tid] = c;
            float s2 = bn2_g[tid] * rsqrtf(bn2_v[tid] + 1e-5f);
            g_bb2[tid] = (b2b[tid] - bn2_m[tid]) * s2 + bn2_b[tid];
        }
    } else {
        int i = (blockIdx.x - 1) * 1024 + tid;
        if (i < NN) g_deg[i] = 0;
    }
}

// ---------------- fused: CSC fill (blocks [0,NB_EDGE)) + gemm1 (rest) ----------------
__global__ void __launch_bounds__(256) k_fillgemm(const int* __restrict__ ei32,
                                                  const float* __restrict__ x,
                                                  const float* __restrict__ w1a) {
    if (blockIdx.x < NB_EDGE) {
        int e = blockIdx.x * 256 + threadIdx.x;
        if (e >= NE) return;
        int s, d;
        if (g_is64) {
            s = ((const int2*)ei32)[e].x;                    // LDG.64, low word
            d = ((const int2*)ei32)[(size_t)NE + e].x;
        } else {
            s = ei32[e];
            d = ei32[NE + e];
        }
        int pos = atomicAdd(&g_deg[d], 1);
        if (pos < CAP) g_slot[(size_t)d * CAP + pos] = s;
        return;
    }

    // ---- gemm1 path ----
    __shared__ float4 ws[FIN * (DIM / 4)];            // 16 KB
    for (int i = threadIdx.x; i < FIN * DIM / 4; i += 256)
        ws[i] = ((const float4*)w1a)[i];
    __syncthreads();

    int n = (blockIdx.x - NB_EDGE) * 256 + threadIdx.x;
    if (n >= NN) return;

    u64 acc[DIM / 2];
#pragma unroll
    for (int j = 0; j < DIM / 2; j++) acc[j] = 0ull;

    const float4* xr = (const float4*)(x + (size_t)n * FIN);
    for (int kk = 0; kk < FIN / 4; kk++) {
        float4 xv = xr[kk];
#pragma unroll
        for (int u = 0; u < 4; u++) {
            float xs = (u == 0) ? xv.x : (u == 1) ? xv.y : (u == 2) ? xv.z : xv.w;
            u64 xs2 = bcast2(xs);
            const ulonglong2* wr = (const ulonglong2*)&ws[(kk * 4 + u) * 8];
#pragma unroll
            for (int j4 = 0; j4 < 8; j4++) {
                ulonglong2 w = wr[j4];
                fma2(acc[2*j4],     xs2, w.x);
                fma2(acc[2*j4 + 1], xs2, w.y);
            }
        }
    }
    u64* yr = (u64*)(g_y + (size_t)n * DIM);
#pragma unroll
    for (int j2 = 0; j2 < 16; j2++) yr[j2] = acc[j2];
}

// ---------------- gather-sum: warp per node, 4 neighbor-groups x 8 float4 lanes ----------------
template <int PASS>
__global__ void __launch_bounds__(256) k_gather() {
    int warp = (blockIdx.x * 256 + threadIdx.x) >> 5;
    int lane = threadIdx.x & 31;
    if (warp >= NN) return;

    const float* feat = (PASS == 0) ? g_y    : g_z;
    float*       agg  = (PASS == 0) ? g_aggY : g_aggZ;

    int grp = lane >> 3;          // neighbor group 0..3
    int col = lane & 7;           // float4 column 0..7

    const int* bucket = &g_slot[(size_t)warp * CAP];
    int cnt = g_deg[warp];
    if (cnt > CAP) cnt = CAP;

    float4 acc = make_float4(0.f, 0.f, 0.f, 0.f);
#pragma unroll 2
    for (int p = 0; p < cnt; p += 4) {
        int nb = p + grp;
        if (nb < cnt) {
            int s = __ldg(&bucket[nb]);                        // 8-lane broadcast
            float4 v = __ldg((const float4*)(feat + (size_t)s * DIM) + col);
            acc.x += v.x; acc.y += v.y; acc.z += v.z; acc.w += v.w;
        }
    }
#pragma unroll
    for (int off = 16; off >= 8; off >>= 1) {
        acc.x += __shfl_xor_sync(0xffffffffu, acc.x, off);
        acc.y += __shfl_xor_sync(0xffffffffu, acc.y, off);
        acc.z += __shfl_xor_sync(0xffffffffu, acc.z, off);
        acc.w += __shfl_xor_sync(0xffffffffu, acc.w, off);
    }
    if (grp == 0)
        ((float4*)(agg + (size_t)warp * DIM))[col] = acc;
}

// ---------------- K3: 2 nodes/thread, smem-staged activations, shared weight loads ----------------
// 128 threads, 256 nodes/block. Thread t owns smem slots t and 128+t (stride SAS,
// conflict-free, thread-private -> no syncs around the staging).
__global__ void __launch_bounds__(128) k_mlp1(const float* __restrict__ b1a,
                                              const float* __restrict__ w1b,
                                              const float* __restrict__ b1b) {
    __shared__ float4 w1b_s[DIM * 8];
    __shared__ float4 w2a_s[DIM * 8];
    __shared__ float b1a_s[DIM], b1b_s[DIM], c2a_s[DIM];
    __shared__ float sbuf[256 * SAS];                 // 33.8 KB
    int t = threadIdx.x;
    for (int i = t; i < DIM * 8; i += 128) {
        w1b_s[i] = ((const float4*)w1b)[i];
        w2a_s[i] = ((const float4*)g_W2a)[i];
    }
    if (t < DIM) { b1a_s[t] = b1a[t]; b1b_s[t] = b1b[t]; c2a_s[t] = g_c2a[t]; }
    __syncthreads();

    int base = blockIdx.x * 256;
    int nA = base + t, nB = base + 128 + t;
    bool vA = nA < NN, vB = nB < NN;
    size_t cA = vA ? (size_t)nA : 0, cB = vB ? (size_t)nB : 0;
    float* sA = &sbuf[t * SAS];
    float* sB = &sbuf[(128 + t) * SAS];

    // phase A: tin = relu(agg + y + b1a) for both nodes -> smem
    {
        const float4* ay = (const float4*)(g_aggY + cA * DIM);
        const float4* yy = (const float4*)(g_y    + cA * DIM);
#pragma unroll
        for (int i = 0; i < 8; i++) {
            float4 a = ay[i], b = yy[i];
            sA[i*4+0] = fmaxf(a.x + b.x + b1a_s[i*4+0], 0.f);
            sA[i*4+1] = fmaxf(a.y + b.y + b1a_s[i*4+1], 0.f);
            sA[i*4+2] = fmaxf(a.z + b.z + b1a_s[i*4+2], 0.f);
            sA[i*4+3] = fmaxf(a.w + b.w + b1a_s[i*4+3], 0.f);
        }
        ay = (const float4*)(g_aggY + cB * DIM);
        yy = (const float4*)(g_y    + cB * DIM);
#pragma unroll
        for (int i = 0; i < 8; i++) {
            float4 a = ay[i], b = yy[i];
            sB[i*4+0] = fmaxf(a.x + b.x + b1a_s[i*4+0], 0.f);
            sB[i*4+1] = fmaxf(a.y + b.y + b1a_s[i*4+1], 0.f);
            sB[i*4+2] = fmaxf(a.z + b.z + b1a_s[i*4+2], 0.f);
            sB[i*4+3] = fmaxf(a.w + b.w + b1a_s[i*4+3], 0.f);
        }
    }

    // phase B: h = relu(tin @ w1b + b1b), shared weight loads
    {
        u64 hA[16], hB[16];
#pragma unroll
        for (int j = 0; j < 16; j++) {
            u64 b = pk2(b1b_s[2*j], b1b_s[2*j+1]);
            hA[j] = b; hB[j] = b;
        }
#pragma unroll
        for (int k = 0; k < DIM; k++) {
            u64 a2 = bcast2(sA[k]);
            u64 b2 = bcast2(sB[k]);
            const ulonglong2* wr = (const ulonglong2*)&w1b_s[k * 8];
#pragma unroll
            for (int j4 = 0; j4 < 8; j4++) {
                ulonglong2 w = wr[j4];
                fma2(hA[2*j4],     a2, w.x);
                fma2(hA[2*j4 + 1], a2, w.y);
                fma2(hB[2*j4],     b2, w.x);
                fma2(hB[2*j4 + 1], b2, w.y);
            }
        }
#pragma unroll
        for (int j = 0; j < 16; j++) {
            float2 fa = up2(hA[j]), fb = up2(hB[j]);
            sA[2*j]   = fmaxf(fa.x, 0.f);
            sA[2*j+1] = fmaxf(fa.y, 0.f);
            sB[2*j]   = fmaxf(fb.x, 0.f);
            sB[2*j+1] = fmaxf(fb.y, 0.f);
        }
    }

    // phase C: z = h @ W2a' + c2a -> global
    {
        u64 zA[16], zB[16];
#pragma unroll
        for (int j = 0; j < 16; j++) {
            u64 b = pk2(c2a_s[2*j], c2a_s[2*j+1]);
            zA[j] = b; zB[j] = b;
        }
#pragma unroll
        for (int k = 0; k < DIM; k++) {
            u64 a2 = bcast2(sA[k]);
            u64 b2 = bcast2(sB[k]);
            const ulonglong2* wr = (const ulonglong2*)&w2a_s[k * 8];
#pragma unroll
            for (int j4 = 0; j4 < 8; j4++) {
                ulonglong2 w = wr[j4];
                fma2(zA[2*j4],     a2, w.x);
                fma2(zA[2*j4 + 1], a2, w.y);
                fma2(zB[2*j4],     b2, w.x);
                fma2(zB[2*j4 + 1], b2, w.y);
            }
        }
        if (vA) {
            u64* zr = (u64*)(g_z + (size_t)nA * DIM);
#pragma unroll
            for (int j = 0; j < 16; j++) zr[j] = zA[j];
        }
        if (vB) {
            u64* zr = (u64*)(g_z + (size_t)nB * DIM);
#pragma unroll
            for (int j = 0; j < 16; j++) zr[j] = zB[j];
        }
    }
}

// ---------------- K5: 2 nodes/thread epilogue + per-node log_softmax ----------------
__global__ void __launch_bounds__(128) k_final(const float* __restrict__ b2a,
                                               const float* __restrict__ fc1_w,
                                               const float* __restrict__ fc1_b,
                                               const float* __restrict__ fc2_w,
                                               const float* __restrict__ fc2_b,
                                               float* __restrict__ out) {
    __shared__ float4 w2b_s[DIM * 8];
    __shared__ float4 fc1_s[DIM * 8];
    __shared__ float4 fc2_s[DIM * NC / 4];
    __shared__ float b2a_s[DIM], bb2_s[DIM], fc1b_s[DIM], fc2b_s[NC];
    __shared__ float sbuf[256 * SAS];                 // 33.8 KB (total ~47.6 KB)
    int t = threadIdx.x;
    for (int i = t; i < DIM * 8; i += 128) {
        w2b_s[i] = ((const float4*)g_W2b)[i];
        fc1_s[i] = ((const float4*)fc1_w)[i];
    }
    for (int i = t; i < DIM * NC / 4; i += 128)
        fc2_s[i] = ((const float4*)fc2_w)[i];
    if (t < DIM) { b2a_s[t] = b2a[t]; bb2_s[t] = g_bb2[t]; fc1b_s[t] = fc1_b[t]; }
    if (t < NC)  fc2b_s[t] = fc2_b[t];
    __syncthreads();

    int base = blockIdx.x * 256;
    int nA = base + t, nB = base + 128 + t;
    bool vA = nA < NN, vB = nB < NN;
    size_t cA = vA ? (size_t)nA : 0, cB = vB ? (size_t)nB : 0;
    float* sA = &sbuf[t * SAS];
    float* sB = &sbuf[(128 + t) * SAS];

    // phase A: q = relu(aggZ + z + b2a) -> smem
    {
        const float4* az = (const float4*)(g_aggZ + cA * DIM);
        const float4* zz = (const float4*)(g_z    + cA * DIM);
#pragma unroll
        for (int i = 0; i < 8; i++) {
            float4 a = az[i], b = zz[i];
            sA[i*4+0] = fmaxf(a.x + b.x + b2a_s[i*4+0], 0.f);
            sA[i*4+1] = fmaxf(a.y + b.y + b2a_s[i*4+1], 0.f);
            sA[i*4+2] = fmaxf(a.z + b.z + b2a_s[i*4+2], 0.f);
            sA[i*4+3] = fmaxf(a.w + b.w + b2a_s[i*4+3], 0.f);
        }
        az = (const float4*)(g_aggZ + cB * DIM);
        zz = (const float4*)(g_z    + cB * DIM);
#pragma unroll
        for (int i = 0; i < 8; i++) {
            float4 a = az[i], b = zz[i];
            sB[i*4+0] = fmaxf(a.x + b.x + b2a_s[i*4+0], 0.f);
            sB[i*4+1] = fmaxf(a.y + b.y + b2a_s[i*4+1], 0.f);
            sB[i*4+2] = fmaxf(a.z + b.z + b2a_s[i*4+2], 0.f);
            sB[i*4+3] = fmaxf(a.w + b.w + b2a_s[i*4+3], 0.f);
        }
    }

    // phase B: u = q @ W2b' + b2b' (no relu), shared weights
    {
        u64 uA[16], uB[16];
#pragma unroll
        for (int j = 0; j < 16; j++) {
            u64 b = pk2(bb2_s[2*j], bb2_s[2*j+1]);
            uA[j] = b; uB[j] = b;
        }
#pragma unroll
        for (int k = 0; k < DIM; k++) {
            u64 a2 = bcast2(sA[k]);
            u64 b2 = bcast2(sB[k]);
            const ulonglong2* wr = (const ulonglong2*)&w2b_s[k * 8];
#pragma unroll
            for (int j4 = 0; j4 < 8; j4++) {
                ulonglong2 w = wr[j4];
                fma2(uA[2*j4],     a2, w.x);
                fma2(uA[2*j4 + 1], a2, w.y);
                fma2(uB[2*j4],     b2, w.x);
                fma2(uB[2*j4 + 1], b2, w.y);
            }
        }
#pragma unroll
        for (int j = 0; j < 16; j++) {
            float2 fa = up2(uA[j]), fb = up2(uB[j]);
            sA[2*j] = fa.x; sA[2*j+1] = fa.y;
            sB[2*j] = fb.x; sB[2*j+1] = fb.y;
        }
    }

    // phase C: r = relu(u @ fc1_w + fc1_b), shared weights
    {
        u64 rA[16], rB[16];
#pragma unroll
        for (int j = 0; j < 16; j++) {
            u64 b = pk2(fc1b_s[2*j], fc1b_s[2*j+1]);
            rA[j] = b; rB[j] = b;
        }
#pragma unroll
        for (int k = 0; k < DIM; k++) {
            u64 a2 = bcast2(sA[k]);
            u64 b2 = bcast2(sB[k]);
            const ulonglong2* wr = (const ulonglong2*)&fc1_s[k * 8];
#pragma unroll
            for (int j4 = 0; j4 < 8; j4++) {
                ulonglong2 w = wr[j4];
                fma2(rA[2*j4],     a2, w.x);
                fma2(rA[2*j4 + 1], a2, w.y);
                fma2(rB[2*j4],     b2, w.x);
                fma2(rB[2*j4 + 1], b2, w.y);
            }
        }
#pragma unroll
        for (int j = 0; j < 16; j++) {
            float2 fa = up2(rA[j]), fb = up2(rB[j]);
            sA[2*j]   = fmaxf(fa.x, 0.f);
            sA[2*j+1] = fmaxf(fa.y, 0.f);
            sB[2*j]   = fmaxf(fb.x, 0.f);
            sB[2*j+1] = fmaxf(fb.y, 0.f);
        }
    }

    // phase D: per-node logits (32x40) + log_softmax (keeps live regs low)
#pragma unroll 1
    for (int which = 0; which < 2; which++) {
        bool v = which ? vB : vA;
        if (!v) continue;
        const float* sr = which ? sB : sA;
        int n = which ? nB : nA;

        u64 l[NC / 2];
#pragma unroll
        for (int c = 0; c < NC / 2; c++) l[c] = pk2(fc2b_s[2*c], fc2b_s[2*c+1]);
#pragma unroll
        for (int k = 0; k < DIM; k++) {
            u64 rk2 = bcast2(sr[k]);
            const ulonglong2* wr = (const ulonglong2*)&fc2_s[k * (NC / 4)];
#pragma unroll
            for (int c2 = 0; c2 < NC / 4; c2++) {    // 10 ulonglong2 per row
                ulonglong2 w = wr[c2];
                fma2(l[2*c2],     rk2, w.x);
                fma2(l[2*c2 + 1], rk2, w.y);
            }
        }
        float lf[NC];
#pragma unroll
        for (int c2 = 0; c2 < NC / 2; c2++) {
            float2 f = up2(l[c2]);
            lf[2*c2] = f.x; lf[2*c2+1] = f.y;
        }

        float m = lf[0];
#pragma unroll
        for (int c = 1; c < NC; c++) m = fmaxf(m, lf[c]);
        float ssum = 0.f;
#pragma unroll
        for (int c = 0; c < NC; c++) ssum += expf(lf[c] - m);
        float lse = m + logf(ssum);

        float4* orow = (float4*)(out + (size_t)n * NC);
#pragma unroll
        for (int c4 = 0; c4 < NC / 4; c4++)
            orow[c4] = make_float4(lf[c4*4+0]-lse, lf[c4*4+1]-lse,
                                   lf[c4*4+2]-lse, lf[c4*4+3]-lse);
    }
}

// ---------------- launch ----------------
extern "C" void kernel_launch(void* const* d_in, const int* in_sizes, int n_in,
                              void* d_out, int out_size) {
    const float* x     = (const float*)d_in[0];
    const int*   ei32  = (const int*)d_in[1];       // int32 OR int64 (detected on device)
    const float* w1a   = (const float*)d_in[2];
    const float* b1a   = (const float*)d_in[3];
    const float* w1b   = (const float*)d_in[4];
    const float* b1b   = (const float*)d_in[5];
    const float* w2a   = (const float*)d_in[6];
    const float* b2a   = (const float*)d_in[7];
    const float* w2b   = (const float*)d_in[8];
    const float* b2b   = (const float*)d_in[9];
    const float* bn1_g = (const float*)d_in[10];
    const float* bn1_b = (const float*)d_in[11];
    const float* bn1_m = (const float*)d_in[12];
    const float* bn1_v = (const float*)d_in[13];
    const float* bn2_g = (const float*)d_in[14];
    const float* bn2_b = (const float*)d_in[15];
    const float* bn2_m = (const float*)d_in[16];
    const float* bn2_v = (const float*)d_in[17];
    const float* fc1_w = (const float*)d_in[18];
    const float* fc1_b = (const float*)d_in[19];
    const float* fc2_w = (const float*)d_in[20];
    const float* fc2_b = (const float*)d_in[21];
    float* out = (float*)d_out;

    const int NB_WARP = (NN * 32 + 255) / 256;      // 12500, warp per node
    const int NB_INIT = 1 + (NN + 1023) / 1024;     // 99
    const int NB_PAIR = (NN + 255) / 256;           // 391 (256 nodes per 128-thread block)

    // 6 launches; profiled (4th) launch is k_mlp1 (verifying 2-nodes/thread win)
    k_initsetup<<<NB_INIT, 1024>>>(ei32, w2a, bn1_g, bn1_b, bn1_m, bn1_v,
                                   w2b, b2b, bn2_g, bn2_b, bn2_m, bn2_v);
    k_fillgemm<<<NB_EDGE + NB_NODE, 256>>>(ei32, x, w1a);
    k_gather<0><<<NB_WARP, 256>>>();
    k_mlp1<<<NB_PAIR, 128>>>(b1a, w1b, b1b);
    k_gather<1><<<NB_WARP, 256>>>();
    k_final<<<NB_PAIR, 128>>>(b2a, fc1_w, fc1_b, fc2_w, fc2_b, out);
}